// round 2
// baseline (speedup 1.0000x reference)
#include <cuda_runtime.h>
#include <math.h>
#include <mma.h>
using namespace nvcuda;

#define Bz   64
#define Lz   25
#define Fz   128
#define Pz   10000
#define Cz   400
#define BL   1600
#define PEPAD 10240
#define NBLK 128        // mega-kernel grid (2 blocks per batch)

// ---------------- device scratch -------------------------------------------------
__device__ __align__(16) float g_buf0[BL * Fz];
__device__ __align__(16) float g_buf1[BL * Fz];
__device__ __align__(16) float g_buf2[BL * Fz];
__device__ __align__(16) float g_buf3[BL * Fz];
__device__ __align__(16) float g_ag[BL * Fz];
__device__ __align__(16) float g_pe[PEPAD * Fz];
__device__ float g_meanp[2 * Bz * Lz];     // [h][b][tau]
__device__ unsigned g_maxbits = 0u;
__device__ unsigned g_minbits = 0x7F7FFFFFu;
__device__ unsigned g_gen = 0u;
__device__ unsigned g_cnt = 0u;

// ---------------- embeddings -----------------------------------------------------
__global__ void k_embed(const int* __restrict__ user, const int* __restrict__ poi,
                        const int* __restrict__ cat,  const int* __restrict__ tod,
                        const int* __restrict__ dow,
                        const float* __restrict__ ue,  const float* __restrict__ pe,
                        const float* __restrict__ ce,  const float* __restrict__ te,
                        const float* __restrict__ de,  const float* __restrict__ uec,
                        const float* __restrict__ tec, const float* __restrict__ dec) {
    int r = blockIdx.x, t = threadIdx.x;
    int u = user[r], p = poi[r], c = cat[r], td = tod[r], dw = dow[r];
    g_buf0[r * Fz + t] = ue[u * Fz + t]  + pe[p * Fz + t] + te[td * Fz + t]  + de[dw * Fz + t];
    g_buf1[r * Fz + t] = uec[u * Fz + t] + ce[c * Fz + t] + tec[td * Fz + t] + dec[dw * Fz + t];
}

// ---------------- pad + tf32-round poi_emb ---------------------------------------
__global__ void k_padpe(const float* __restrict__ pe) {
    int r = blockIdx.x, t = threadIdx.x;
    float v = 0.f;
    if (r < Pz) v = wmma::__float_to_tf32(pe[r * Fz + t]);
    g_pe[r * Fz + t] = v;
}

// ---------------- min/max over gathered D rows (idempotent across replays) ------
__global__ void k_minmax(const int* __restrict__ poi, const float* __restrict__ Dm) {
    __shared__ float smx[256], smn[256];
    int t = threadIdx.x;
    int row = poi[blockIdx.x];
    const float* rp = Dm + (size_t)row * Pz;
    float mx = -1e30f, mn = 1e30f;
    for (int p = t; p < Pz; p += 256) { float v = rp[p]; mx = fmaxf(mx, v); mn = fminf(mn, v); }
    smx[t] = mx; smn[t] = mn; __syncthreads();
    for (int s = 128; s > 0; s >>= 1) {
        if (t < s) { smx[t] = fmaxf(smx[t], smx[t + s]); smn[t] = fminf(smn[t], smn[t + s]); }
        __syncthreads();
    }
    if (t == 0) {
        atomicMax(&g_maxbits, __float_as_uint(smx[0]));
        atomicMin(&g_minbits, __float_as_uint(smn[0]));
    }
}

// ---------------- grid barrier (all NBLK blocks co-resident) ---------------------
__device__ __forceinline__ void gridbar() {
    __syncthreads();
    if (threadIdx.x == 0) {
        __threadfence();
        volatile unsigned* vg = &g_gen;
        unsigned gen = *vg;
        unsigned prev = atomicAdd(&g_cnt, 1u);
        if (prev == NBLK - 1) {
            g_cnt = 0u;
            __threadfence();
            *vg = gen + 1u;
        } else {
            while (*vg == gen) { }
        }
        __threadfence();
    }
    __syncthreads();
}

// ---------------- one autocorrelation call (per block: batch b, col-half h) ------
__device__ __noinline__ void do_call(
    const float* __restrict__ qx, const float* __restrict__ kvx,
    float* __restrict__ dst,
    const float* __restrict__ Wc, const float* __restrict__ bc,
    int b, int h,
    float* inq, float* inkv, float* qkv, float* ws,
    float* s_gms, int* s_idx, float* s_tc)
{
    const int t = threadIdx.x;
    // load inputs (cross-block data -> L2 path)
    {
        const float4* q4 = (const float4*)(qx + b * Lz * Fz);
        const float4* k4 = (const float4*)(kvx + b * Lz * Fz);
        for (int i = t; i < Lz * Fz / 4; i += 256) {
            ((float4*)inq)[i]  = __ldcg(q4 + i);
            ((float4*)inkv)[i] = __ldcg(k4 + i);
        }
    }
    __syncthreads();
    const int o_l = t & 63, rg = t >> 6;

    // ---- q,k,v projection for own 64 output cols ----
    for (int m = 0; m < 3; m++) {
        const float* Wm = Wc + m * Fz * Fz + (h * 64) * Fz;
        const float* inp = (m == 0) ? inq : inkv;
        float acc[7];
        #pragma unroll
        for (int r = 0; r < 7; r++) acc[r] = 0.f;
        for (int d0 = 0; d0 < 128; d0 += 32) {
            __syncthreads();
            #pragma unroll
            for (int j = 0; j < 2; j++) {
                int ii = t + j * 256;
                int row = ii >> 3, f4 = ii & 7;
                float4 w = *(const float4*)(Wm + row * Fz + d0 + f4 * 4);
                *(float4*)&ws[row * 36 + f4 * 4] = w;
            }
            __syncthreads();
            #pragma unroll
            for (int dd4 = 0; dd4 < 8; dd4++) {
                float4 w4 = *(float4*)&ws[o_l * 36 + dd4 * 4];
                int ri = 0;
                for (int l = rg; l < Lz; l += 4, ri++) {
                    float4 a = *(float4*)&inp[l * Fz + d0 + dd4 * 4];
                    acc[ri] += w4.x * a.x + w4.y * a.y + w4.z * a.z + w4.w * a.w;
                }
            }
        }
        float bias = bc[m * Fz + h * 64 + o_l];
        int ri = 0;
        for (int l = rg; l < Lz; l += 4, ri++)
            qkv[m * 1600 + l * 64 + o_l] = acc[ri] + bias;
    }
    __syncthreads();

    // ---- partial circular correlation over own 64 dims ----
    {
        int wid = t >> 5, lane = t & 31;
        for (int tau = wid; tau < Lz; tau += 8) {
            float s = 0.f;
            for (int idx = lane; idx < 1600; idx += 32) {
                int n = idx >> 6, d = idx & 63;
                int np = n + tau; if (np >= Lz) np -= Lz;
                s += qkv[np * 64 + d] * qkv[1600 + idx];
            }
            #pragma unroll
            for (int o = 16; o > 0; o >>= 1) s += __shfl_down_sync(0xffffffffu, s, o);
            if (lane == 0) g_meanp[h * 1600 + b * Lz + tau] = s;
        }
    }
    gridbar();

    // ---- redundant top-3 + per-batch softmax (inq reused as meanp mirror) ----
    for (int i = t; i < 3200; i += 256) inq[i] = __ldcg(&g_meanp[i]);
    __syncthreads();
    if (t < Lz) {
        float s = 0.f;
        for (int bb = 0; bb < Bz; bb++)
            s += inq[bb * Lz + t] + inq[1600 + bb * Lz + t];
        s_gms[t] = s;
    }
    __syncthreads();
    if (t == 0) {
        int id[3];
        for (int kk = 0; kk < 3; kk++) {
            float best = -1e38f; int bi = 0;
            for (int j = 0; j < Lz; j++) {
                bool used = false;
                for (int q = 0; q < kk; q++) if (id[q] == j) used = true;
                if (!used && s_gms[j] > best) { best = s_gms[j]; bi = j; }
            }
            id[kk] = bi;
        }
        float w0 = (inq[b * Lz + id[0]] + inq[1600 + b * Lz + id[0]]) * (1.f / 128.f);
        float w1 = (inq[b * Lz + id[1]] + inq[1600 + b * Lz + id[1]]) * (1.f / 128.f);
        float w2 = (inq[b * Lz + id[2]] + inq[1600 + b * Lz + id[2]]) * (1.f / 128.f);
        float mx = fmaxf(w0, fmaxf(w1, w2));
        float e0 = expf(w0 - mx), e1 = expf(w1 - mx), e2 = expf(w2 - mx);
        float inv = 1.f / (e0 + e1 + e2);
        s_tc[0] = e0 * inv; s_tc[1] = e1 * inv; s_tc[2] = e2 * inv;
        s_idx[0] = id[0]; s_idx[1] = id[1]; s_idx[2] = id[2];
    }
    __syncthreads();

    // ---- lag aggregation (own cols) -> g_ag ----
    {
        int i0 = s_idx[0], i1 = s_idx[1], i2 = s_idx[2];
        float c0 = s_tc[0], c1 = s_tc[1], c2 = s_tc[2];
        for (int idx = t; idx < 1600; idx += 256) {
            int l = idx >> 6, d = idx & 63;
            int p0 = l + i0; if (p0 >= Lz) p0 -= Lz;
            int p1 = l + i1; if (p1 >= Lz) p1 -= Lz;
            int p2 = l + i2; if (p2 >= Lz) p2 -= Lz;
            g_ag[b * 3200 + l * Fz + h * 64 + d] =
                c0 * qkv[3200 + p0 * 64 + d] + c1 * qkv[3200 + p1 * 64 + d] + c2 * qkv[3200 + p2 * 64 + d];
        }
    }
    gridbar();

    // ---- output projection: full ag x W3^T, own 64 output cols ----
    {
        const float4* a4 = (const float4*)(g_ag + b * 3200);
        for (int i = t; i < 800; i += 256) ((float4*)inq)[i] = __ldcg(a4 + i);
    }
    __syncthreads();
    {
        const float* Wm = Wc + 3 * Fz * Fz + (h * 64) * Fz;
        float acc[7];
        #pragma unroll
        for (int r = 0; r < 7; r++) acc[r] = 0.f;
        for (int d0 = 0; d0 < 128; d0 += 32) {
            __syncthreads();
            #pragma unroll
            for (int j = 0; j < 2; j++) {
                int ii = t + j * 256;
                int row = ii >> 3, f4 = ii & 7;
                float4 w = *(const float4*)(Wm + row * Fz + d0 + f4 * 4);
                *(float4*)&ws[row * 36 + f4 * 4] = w;
            }
            __syncthreads();
            #pragma unroll
            for (int dd4 = 0; dd4 < 8; dd4++) {
                float4 w4 = *(float4*)&ws[o_l * 36 + dd4 * 4];
                int ri = 0;
                for (int l = rg; l < Lz; l += 4, ri++) {
                    float4 a = *(float4*)&inq[l * Fz + d0 + dd4 * 4];
                    acc[ri] += w4.x * a.x + w4.y * a.y + w4.z * a.z + w4.w * a.w;
                }
            }
        }
        float bias = bc[3 * Fz + h * 64 + o_l];
        int ri = 0;
        for (int l = rg; l < Lz; l += 4, ri++)
            dst[(b * Lz + l) * Fz + h * 64 + o_l] = acc[ri] + bias;
    }
    gridbar();
}

// ---------------- all 8 layer-calls, one launch ---------------------------------
__global__ void __launch_bounds__(256) k_layers(const float* __restrict__ W,
                                                const float* __restrict__ Bv) {
    extern __shared__ float sm[];
    float* inq  = sm;           // 3200
    float* inkv = sm + 3200;    // 3200
    float* qkv  = sm + 6400;    // 4800 (q,k,v own halves)
    float* ws   = sm + 11200;   // 64*36 = 2304
    __shared__ float s_gms[Lz];
    __shared__ int   s_idx[3];
    __shared__ float s_tc[3];

    int b = blockIdx.x >> 1, h = blockIdx.x & 1;
    float* cur  = g_buf0; float* alt  = g_buf2;
    float* curc = g_buf1; float* altc = g_buf3;
    float* tmp;

    for (int i = 0; i < 2; i++) {
        const float* Wl = W  + (size_t)i * 4 * 4 * Fz * Fz;
        const float* Bl = Bv + (size_t)i * 4 * 4 * Fz;
        do_call(cur,  cur,  alt,  Wl + 0 * 4 * Fz * Fz, Bl + 0 * 4 * Fz, b, h, inq, inkv, qkv, ws, s_gms, s_idx, s_tc);
        tmp = cur;  cur  = alt;  alt  = tmp;
        do_call(curc, curc, altc, Wl + 1 * 4 * Fz * Fz, Bl + 1 * 4 * Fz, b, h, inq, inkv, qkv, ws, s_gms, s_idx, s_tc);
        tmp = curc; curc = altc; altc = tmp;
        do_call(cur,  curc, alt,  Wl + 2 * 4 * Fz * Fz, Bl + 2 * 4 * Fz, b, h, inq, inkv, qkv, ws, s_gms, s_idx, s_tc);
        tmp = cur;  cur  = alt;  alt  = tmp;
        do_call(curc, cur,  altc, Wl + 3 * 4 * Fz * Fz, Bl + 3 * 4 * Fz, b, h, inq, inkv, qkv, ws, s_gms, s_idx, s_tc);
        tmp = curc; curc = altc; altc = tmp;
    }
    // final: out = g_buf0, outc = g_buf1
}

// ---------------- final POI scoring: tf32 WMMA + fused exp-gather epilogue -------
// grid (40, 32): 2 batches per block (M=64), N-tile 256, K=128
__global__ void __launch_bounds__(256) k_final_poi(
        const float* __restrict__ outp, const int* __restrict__ poi,
        const float* __restrict__ Dm,   const float* __restrict__ vw,
        const float* __restrict__ vbp,  float* __restrict__ dst) {
    extern __shared__ float sm[];       // 64*264 floats; A phase uses first 64*128
    float* a_s = sm;
    float* S   = sm;
    __shared__ int   rows_s[50];
    __shared__ float vws[Lz];

    int t = threadIdx.x, wid = t >> 5;
    int ptile = blockIdx.x, b0 = blockIdx.y * 2;

    for (int i = t; i < 64 * 128; i += 256) {
        int r = i >> 7, d = i & 127;
        int l = r & 31, bb = b0 + (r >> 5);
        float v = 0.f;
        if (l < Lz) v = wmma::__float_to_tf32(outp[((bb * Lz) + l) * Fz + d]);
        a_s[i] = v;
    }
    if (t < 50) rows_s[t] = poi[(b0 + t / Lz) * Lz + (t % Lz)];
    if (t < Lz) vws[t] = vw[t];
    __syncthreads();

    wmma::fragment<wmma::matrix_a, 16, 16, 8, wmma::precision::tf32, wmma::row_major> fa;
    wmma::fragment<wmma::matrix_b, 16, 16, 8, wmma::precision::tf32, wmma::col_major> fb0, fb1;
    wmma::fragment<wmma::accumulator, 16, 16, 8, float> facc[4][2];
    #pragma unroll
    for (int m = 0; m < 4; m++) { wmma::fill_fragment(facc[m][0], 0.f); wmma::fill_fragment(facc[m][1], 0.f); }

    const float* peB = g_pe + (size_t)(ptile * 256) * Fz;
    for (int k = 0; k < 128; k += 8) {
        wmma::load_matrix_sync(fb0, peB + (size_t)((wid * 2 + 0) * 16) * Fz + k, Fz);
        wmma::load_matrix_sync(fb1, peB + (size_t)((wid * 2 + 1) * 16) * Fz + k, Fz);
        #pragma unroll
        for (int m = 0; m < 4; m++) {
            wmma::load_matrix_sync(fa, a_s + (m * 16) * Fz + k, Fz);
            wmma::mma_sync(facc[m][0], fa, fb0, facc[m][0]);
            wmma::mma_sync(facc[m][1], fa, fb1, facc[m][1]);
        }
    }
    __syncthreads();   // A no longer needed; S overlays it
    #pragma unroll
    for (int m = 0; m < 4; m++) {
        wmma::store_matrix_sync(S + (m * 16) * 264 + (wid * 2 + 0) * 16, facc[m][0], 264, wmma::mem_row_major);
        wmma::store_matrix_sync(S + (m * 16) * 264 + (wid * 2 + 1) * 16, facc[m][1], 264, wmma::mem_row_major);
    }
    __syncthreads();

    int p = ptile * 256 + t;
    if (p < Pz) {
        float neginv = -1.f / (__uint_as_float(g_maxbits) - __uint_as_float(g_minbits));
        float bias = vbp[0];
        #pragma unroll
        for (int bb = 0; bb < 2; bb++) {
            float r = 0.f;
            #pragma unroll
            for (int l = 0; l < Lz; l++) {
                float s = S[(bb * 32 + l) * 264 + t];
                float d = Dm[(size_t)rows_s[bb * Lz + l] * Pz + p];
                r += s * __expf(d * neginv) * vws[l];
            }
            dst[(size_t)(b0 + bb) * Pz + p] = r + bias;
        }
    }
}

// ---------------- final CAT scoring ----------------------------------------------
__global__ void k_final_cat(const float* __restrict__ outcp, const float* __restrict__ ce,
                            const float* __restrict__ vw, const float* __restrict__ vbp,
                            float* __restrict__ dst) {
    __shared__ __align__(16) float y[Fz];
    int b = blockIdx.x, t = threadIdx.x;
    float s = 0.f;
    for (int l = 0; l < Lz; l++) s += vw[l] * outcp[(b * Lz + l) * Fz + t];
    y[t] = s;
    __syncthreads();
    const float4* Y4 = (const float4*)y;
    float bias = vbp[0];
    for (int g = 0; g < 4; g++) {
        int c = g * 128 + t;
        if (c < Cz) {
            const float4* C4 = (const float4*)(ce + c * Fz);
            float acc = 0.f;
            for (int q = 0; q < 32; q++) {
                float4 cv = C4[q], yv = Y4[q];
                acc += cv.x * yv.x + cv.y * yv.y + cv.z * yv.z + cv.w * yv.w;
            }
            dst[b * Cz + c] = acc + bias;
        }
    }
}

// ---------------- host driver ----------------------------------------------------
extern "C" void kernel_launch(void* const* d_in, const int* in_sizes, int n_in,
                              void* d_out, int out_size) {
    const int*   user = (const int*)d_in[0];
    const int*   poi  = (const int*)d_in[1];
    const int*   cat  = (const int*)d_in[2];
    const int*   tod  = (const int*)d_in[5];
    const int*   dow  = (const int*)d_in[6];
    const float* ue   = (const float*)d_in[8];
    const float* pe   = (const float*)d_in[9];
    const float* ce   = (const float*)d_in[10];
    const float* te   = (const float*)d_in[11];
    const float* de   = (const float*)d_in[12];
    const float* uec  = (const float*)d_in[13];
    const float* tec  = (const float*)d_in[14];
    const float* dec  = (const float*)d_in[15];
    const float* W    = (const float*)d_in[16];
    const float* Bvv  = (const float*)d_in[17];
    const float* vw   = (const float*)d_in[18];
    const float* vb   = (const float*)d_in[19];
    const float* Dm   = (const float*)d_in[20];
    float* out = (float*)d_out;

    static int attr_done = 0;
    if (!attr_done) {
        cudaFuncSetAttribute(k_layers,    cudaFuncAttributeMaxDynamicSharedMemorySize, 56 * 1024);
        cudaFuncSetAttribute(k_final_poi, cudaFuncAttributeMaxDynamicSharedMemorySize, 70 * 1024);
        attr_done = 1;
    }

    float *b0p, *b1p;
    cudaGetSymbolAddress((void**)&b0p, g_buf0);
    cudaGetSymbolAddress((void**)&b1p, g_buf1);

    k_embed<<<BL, Fz>>>(user, poi, cat, tod, dow, ue, pe, ce, te, de, uec, tec, dec);
    k_padpe<<<PEPAD, Fz>>>(pe);
    k_minmax<<<BL, 256>>>(poi, Dm);
    k_layers<<<NBLK, 256, 13504 * 4>>>(W, Bvv);
    k_final_poi<<<dim3(40, 32), 256, 64 * 264 * 4>>>(b0p, poi, Dm, vw, vb, out);
    k_final_cat<<<Bz, 128>>>(b1p, ce, vw, vb, out + (size_t)Bz * Pz);
}